// round 1
// baseline (speedup 1.0000x reference)
#include <cuda_runtime.h>
#include <math.h>

#define SEQ 2048
#define DM  1024
#define NB  4
#define BM 128
#define BN 128
#define BK 16

// ---- scratch (static device globals; no allocation) ----
__device__ float g_qpe[(size_t)SEQ * DM];
__device__ float g_kpe[(size_t)SEQ * DM];
__device__ float g_bias[(size_t)SEQ * SEQ];
__device__ float g_scores[(size_t)NB * SEQ * SEQ];

// ---------------------------------------------------------------------------
// Tiled fp32 GEMM: C[M,N] = alpha * (A @ op(B) [+ bias])
//   B_NT=1 : B is [N,K] row-major (B transposed, i.e. C = A @ B^T)
//   B_NT=0 : B is [K,N] row-major
//   TRANS=1: store C transposed: C[n*M + m]
//   BIASED=1: epilogue adds bias[m*N+n] before alpha scaling
// Tiles: BM=BN=128, BK=16, 256 threads, 8x8 per-thread microtile.
// Requires M%128==0, N%128==0, K%16==0 (true for all uses here).
// ---------------------------------------------------------------------------
template<int B_NT, int TRANS, int BIASED>
__global__ __launch_bounds__(256)
void sgemm_kernel(const float* __restrict__ A, long long sA,
                  const float* __restrict__ B, long long sB,
                  float* __restrict__ C, long long sC,
                  const float* __restrict__ bias,
                  int M, int N, int K, float alpha)
{
    A += (long long)blockIdx.z * sA;
    B += (long long)blockIdx.z * sB;
    C += (long long)blockIdx.z * sC;

    __shared__ float As[BK][BM];
    __shared__ float Bs[BK][BN];

    const int t  = threadIdx.x;
    const int tx = t & 15;       // 16 cols of threads
    const int ty = t >> 4;       // 16 rows of threads
    const int bm = blockIdx.y * BM;
    const int bn = blockIdx.x * BN;

    float acc[8][8];
#pragma unroll
    for (int i = 0; i < 8; i++)
#pragma unroll
        for (int j = 0; j < 8; j++) acc[i][j] = 0.f;

    for (int kt = 0; kt < K; kt += BK) {
        // --- load A tile: A[M,K] row-major -> As[k][m]
#pragma unroll
        for (int it = 0; it < 2; it++) {
            int idx = t + it * 256;            // 512 float4 total
            int row = idx >> 2;
            int c4  = (idx & 3) << 2;
            float4 v4 = *(const float4*)(A + (size_t)(bm + row) * K + kt + c4);
            As[c4 + 0][row] = v4.x;
            As[c4 + 1][row] = v4.y;
            As[c4 + 2][row] = v4.z;
            As[c4 + 3][row] = v4.w;
        }
        // --- load B tile
        if (B_NT) {
            // B[N,K] row-major -> Bs[k][n]
#pragma unroll
            for (int it = 0; it < 2; it++) {
                int idx = t + it * 256;
                int row = idx >> 2;
                int c4  = (idx & 3) << 2;
                float4 v4 = *(const float4*)(B + (size_t)(bn + row) * K + kt + c4);
                Bs[c4 + 0][row] = v4.x;
                Bs[c4 + 1][row] = v4.y;
                Bs[c4 + 2][row] = v4.z;
                Bs[c4 + 3][row] = v4.w;
            }
        } else {
            // B[K,N] row-major -> Bs[k][n] (direct, vectorized)
#pragma unroll
            for (int it = 0; it < 2; it++) {
                int idx = t + it * 256;
                int kk = idx >> 5;
                int c4 = (idx & 31) << 2;
                *(float4*)&Bs[kk][c4] =
                    *(const float4*)(B + (size_t)(kt + kk) * N + bn + c4);
            }
        }
        __syncthreads();

#pragma unroll
        for (int kk = 0; kk < BK; kk++) {
            float ar[8], br[8];
#pragma unroll
            for (int i = 0; i < 8; i++) ar[i] = As[kk][ty * 8 + i];
#pragma unroll
            for (int j = 0; j < 8; j++) br[j] = Bs[kk][tx * 8 + j];
#pragma unroll
            for (int i = 0; i < 8; i++)
#pragma unroll
                for (int j = 0; j < 8; j++)
                    acc[i][j] = fmaf(ar[i], br[j], acc[i][j]);
        }
        __syncthreads();
    }

    // --- epilogue ---
#pragma unroll
    for (int i = 0; i < 8; i++) {
        int m = bm + ty * 8 + i;
        if (TRANS) {
#pragma unroll
            for (int j = 0; j < 8; j++) {
                int n = bn + tx * 8 + j;
                C[(size_t)n * M + m] = acc[i][j] * alpha;
            }
        } else {
#pragma unroll
            for (int j8 = 0; j8 < 2; j8++) {
                int n = bn + tx * 8 + j8 * 4;
                float4 o;
                o.x = acc[i][j8 * 4 + 0];
                o.y = acc[i][j8 * 4 + 1];
                o.z = acc[i][j8 * 4 + 2];
                o.w = acc[i][j8 * 4 + 3];
                if (BIASED) {
                    float4 bv = *(const float4*)(bias + (size_t)m * N + n);
                    o.x = (o.x + bv.x) * alpha;
                    o.y = (o.y + bv.y) * alpha;
                    o.z = (o.z + bv.z) * alpha;
                    o.w = (o.w + bv.w) * alpha;
                } else {
                    o.x *= alpha; o.y *= alpha; o.z *= alpha; o.w *= alpha;
                }
                *(float4*)(C + (size_t)m * N + n) = o;
            }
        }
    }
}

// ---------------------------------------------------------------------------
// Row softmax over SEQ=2048 elements, in place; optionally mirrors the
// normalized row into attn_out (flat [b,q,k] layout, same row index).
// One block (256 threads) per row, 8 elems/thread.
// ---------------------------------------------------------------------------
__global__ __launch_bounds__(256)
void softmax_kernel(float* __restrict__ scores, float* __restrict__ attn_out)
{
    size_t row = blockIdx.x;
    float* p = scores + row * SEQ;
    const int t = threadIdx.x;
    __shared__ float red[8];

    float v[8];
    float mx = -INFINITY;
#pragma unroll
    for (int i = 0; i < 8; i++) {
        v[i] = p[t + i * 256];
        mx = fmaxf(mx, v[i]);
    }
#pragma unroll
    for (int o = 16; o; o >>= 1) mx = fmaxf(mx, __shfl_xor_sync(0xffffffffu, mx, o));
    if ((t & 31) == 0) red[t >> 5] = mx;
    __syncthreads();
    mx = red[0];
#pragma unroll
    for (int w = 1; w < 8; w++) mx = fmaxf(mx, red[w]);
    __syncthreads();

    float s = 0.f;
#pragma unroll
    for (int i = 0; i < 8; i++) {
        v[i] = expf(v[i] - mx);
        s += v[i];
    }
#pragma unroll
    for (int o = 16; o; o >>= 1) s += __shfl_xor_sync(0xffffffffu, s, o);
    if ((t & 31) == 0) red[t >> 5] = s;
    __syncthreads();
    s = 0.f;
#pragma unroll
    for (int w = 0; w < 8; w++) s += red[w];

    float inv = 1.f / s;
#pragma unroll
    for (int i = 0; i < 8; i++) {
        float a = v[i] * inv;
        p[t + i * 256] = a;
        if (attn_out) attn_out[row * SEQ + t + i * 256] = a;
    }
}

// ---------------------------------------------------------------------------
extern "C" void kernel_launch(void* const* d_in, const int* in_sizes, int n_in,
                              void* d_out, int out_size)
{
    const float* q  = (const float*)d_in[0];
    const float* k  = (const float*)d_in[1];
    const float* v  = (const float*)d_in[2];
    const float* pe = (const float*)d_in[3];  // [10000, 1024]; only first 2048 rows used
    const float* Uq = (const float*)d_in[4];
    const float* Uk = (const float*)d_in[5];
    float* out = (float*)d_out;

    float *qpe, *kpe, *bias, *scores;
    cudaGetSymbolAddress((void**)&qpe,    g_qpe);
    cudaGetSymbolAddress((void**)&kpe,    g_kpe);
    cudaGetSymbolAddress((void**)&bias,   g_bias);
    cudaGetSymbolAddress((void**)&scores, g_scores);

    const float invScale = 1.0f / 11.313708498984761f;  // 1/sqrt(2*64)

    const long long ctxElems  = (long long)NB * SEQ * DM;   //  8388608
    const long long attnElems = (long long)NB * SEQ * SEQ;  // 16777216

    float* ctxOut  = out;
    float* attnOut = nullptr;
    if ((long long)out_size == ctxElems + attnElems) {
        attnOut = out + ctxElems;                    // (context, attn) concatenated
    } else if ((long long)out_size == attnElems) {
        attnOut = out; ctxOut = nullptr;             // attn only
    }                                                // else: context only

    // 1) q_pe = pe[:2048] @ Uq ;  k_pe = pe[:2048] @ Uk      (NN)
    sgemm_kernel<0, 0, 0><<<dim3(DM / BN, SEQ / BM, 1), 256>>>(
        pe, 0, Uq, 0, qpe, 0, nullptr, SEQ, DM, DM, 1.f);
    sgemm_kernel<0, 0, 0><<<dim3(DM / BN, SEQ / BM, 1), 256>>>(
        pe, 0, Uk, 0, kpe, 0, nullptr, SEQ, DM, DM, 1.f);

    // 2) bias = q_pe @ k_pe^T  (NT), computed once for all batches
    sgemm_kernel<1, 0, 0><<<dim3(SEQ / BN, SEQ / BM, 1), 256>>>(
        qpe, 0, kpe, 0, bias, 0, nullptr, SEQ, SEQ, DM, 1.f);

    // 3) scores_b = (q_b @ k_b^T + bias) * invScale   (NT, batched over z)
    sgemm_kernel<1, 0, 1><<<dim3(SEQ / BN, SEQ / BM, NB), 256>>>(
        q, (long long)SEQ * DM, k, (long long)SEQ * DM,
        scores, (long long)SEQ * SEQ, bias,
        SEQ, SEQ, DM, invScale);

    // 4) row softmax in place (mirrors into attn output region if required)
    softmax_kernel<<<NB * SEQ, 256>>>(scores, attnOut);

    // 5) context^T: out[b, d*2048 + q] = sum_k attn[b,q,k] * v[b,k,d]
    //    (NN GEMM with transposed store — implements swapaxes(1,2).reshape)
    if (ctxOut) {
        sgemm_kernel<0, 1, 0><<<dim3(DM / BN, SEQ / BM, NB), 256>>>(
            scores, (long long)SEQ * SEQ, v, (long long)SEQ * DM,
            ctxOut, (long long)SEQ * DM, nullptr,
            SEQ, DM, SEQ, 1.f);
    }
}

// round 2
// speedup vs baseline: 1.0529x; 1.0529x over previous
#include <cuda_runtime.h>
#include <math.h>

#define SEQ 2048
#define DM  1024
#define NB  4
#define BM 128
#define BN 128
#define BK 16

// ---- scratch (static device globals; no allocation) ----
__device__ float g_qpe[(size_t)SEQ * DM];
__device__ float g_kpe[(size_t)SEQ * DM];
__device__ float g_bias[(size_t)SEQ * SEQ];
__device__ float g_scores[(size_t)NB * SEQ * SEQ];

// ---------------------------------------------------------------------------
// Tiled fp32 GEMM: C[M,N] = alpha * (A @ op(B) [+ bias])
//   B_NT=1 : B is [N,K] row-major (B transposed, i.e. C = A @ B^T)
//   B_NT=0 : B is [K,N] row-major
//   TRANS=1: store C transposed: C[n*M + m]
//   BIASED=1: epilogue adds bias[m*N+n] before alpha scaling
// Tiles: BM=BN=128, BK=16, 256 threads, 8x8 per-thread microtile.
// Requires M%128==0, N%128==0, K%16==0 (true for all uses here).
// ---------------------------------------------------------------------------
template<int B_NT, int TRANS, int BIASED>
__global__ __launch_bounds__(256)
void sgemm_kernel(const float* __restrict__ A, long long sA,
                  const float* __restrict__ B, long long sB,
                  float* __restrict__ C, long long sC,
                  const float* __restrict__ bias,
                  int M, int N, int K, float alpha)
{
    A += (long long)blockIdx.z * sA;
    B += (long long)blockIdx.z * sB;
    C += (long long)blockIdx.z * sC;

    __shared__ float As[BK][BM];
    __shared__ float Bs[BK][BN];

    const int t  = threadIdx.x;
    const int tx = t & 15;       // 16 cols of threads
    const int ty = t >> 4;       // 16 rows of threads
    const int bm = blockIdx.y * BM;
    const int bn = blockIdx.x * BN;

    float acc[8][8];
#pragma unroll
    for (int i = 0; i < 8; i++)
#pragma unroll
        for (int j = 0; j < 8; j++) acc[i][j] = 0.f;

    for (int kt = 0; kt < K; kt += BK) {
        // --- load A tile: A[M,K] row-major -> As[k][m]
#pragma unroll
        for (int it = 0; it < 2; it++) {
            int idx = t + it * 256;            // 512 float4 total
            int row = idx >> 2;
            int c4  = (idx & 3) << 2;
            float4 v4 = *(const float4*)(A + (size_t)(bm + row) * K + kt + c4);
            As[c4 + 0][row] = v4.x;
            As[c4 + 1][row] = v4.y;
            As[c4 + 2][row] = v4.z;
            As[c4 + 3][row] = v4.w;
        }
        // --- load B tile
        if (B_NT) {
            // B[N,K] row-major -> Bs[k][n]
#pragma unroll
            for (int it = 0; it < 2; it++) {
                int idx = t + it * 256;
                int row = idx >> 2;
                int c4  = (idx & 3) << 2;
                float4 v4 = *(const float4*)(B + (size_t)(bn + row) * K + kt + c4);
                Bs[c4 + 0][row] = v4.x;
                Bs[c4 + 1][row] = v4.y;
                Bs[c4 + 2][row] = v4.z;
                Bs[c4 + 3][row] = v4.w;
            }
        } else {
            // B[K,N] row-major -> Bs[k][n] (direct, vectorized)
#pragma unroll
            for (int it = 0; it < 2; it++) {
                int idx = t + it * 256;
                int kk = idx >> 5;
                int c4 = (idx & 31) << 2;
                *(float4*)&Bs[kk][c4] =
                    *(const float4*)(B + (size_t)(kt + kk) * N + bn + c4);
            }
        }
        __syncthreads();

#pragma unroll
        for (int kk = 0; kk < BK; kk++) {
            float ar[8], br[8];
#pragma unroll
            for (int i = 0; i < 8; i++) ar[i] = As[kk][ty * 8 + i];
#pragma unroll
            for (int j = 0; j < 8; j++) br[j] = Bs[kk][tx * 8 + j];
#pragma unroll
            for (int i = 0; i < 8; i++)
#pragma unroll
                for (int j = 0; j < 8; j++)
                    acc[i][j] = fmaf(ar[i], br[j], acc[i][j]);
        }
        __syncthreads();
    }

    // --- epilogue ---
#pragma unroll
    for (int i = 0; i < 8; i++) {
        int m = bm + ty * 8 + i;
        if (TRANS) {
#pragma unroll
            for (int j = 0; j < 8; j++) {
                int n = bn + tx * 8 + j;
                C[(size_t)n * M + m] = acc[i][j] * alpha;
            }
        } else {
#pragma unroll
            for (int j8 = 0; j8 < 2; j8++) {
                int n = bn + tx * 8 + j8 * 4;
                float4 o;
                o.x = acc[i][j8 * 4 + 0];
                o.y = acc[i][j8 * 4 + 1];
                o.z = acc[i][j8 * 4 + 2];
                o.w = acc[i][j8 * 4 + 3];
                if (BIASED) {
                    float4 bv = *(const float4*)(bias + (size_t)m * N + n);
                    o.x = (o.x + bv.x) * alpha;
                    o.y = (o.y + bv.y) * alpha;
                    o.z = (o.z + bv.z) * alpha;
                    o.w = (o.w + bv.w) * alpha;
                } else {
                    o.x *= alpha; o.y *= alpha; o.z *= alpha; o.w *= alpha;
                }
                *(float4*)(C + (size_t)m * N + n) = o;
            }
        }
    }
}

// ---------------------------------------------------------------------------
// Row softmax over SEQ=2048 elements, in place; optionally mirrors the
// normalized row into attn_out (flat [b,q,k] layout, same row index).
// One block (256 threads) per row, 8 elems/thread.
// ---------------------------------------------------------------------------
__global__ __launch_bounds__(256)
void softmax_kernel(float* __restrict__ scores, float* __restrict__ attn_out)
{
    size_t row = blockIdx.x;
    float* p = scores + row * SEQ;
    const int t = threadIdx.x;
    __shared__ float red[8];

    float v[8];
    float mx = -INFINITY;
#pragma unroll
    for (int i = 0; i < 8; i++) {
        v[i] = p[t + i * 256];
        mx = fmaxf(mx, v[i]);
    }
#pragma unroll
    for (int o = 16; o; o >>= 1) mx = fmaxf(mx, __shfl_xor_sync(0xffffffffu, mx, o));
    if ((t & 31) == 0) red[t >> 5] = mx;
    __syncthreads();
    mx = red[0];
#pragma unroll
    for (int w = 1; w < 8; w++) mx = fmaxf(mx, red[w]);
    __syncthreads();

    float s = 0.f;
#pragma unroll
    for (int i = 0; i < 8; i++) {
        v[i] = expf(v[i] - mx);
        s += v[i];
    }
#pragma unroll
    for (int o = 16; o; o >>= 1) s += __shfl_xor_sync(0xffffffffu, s, o);
    if ((t & 31) == 0) red[t >> 5] = s;
    __syncthreads();
    s = 0.f;
#pragma unroll
    for (int w = 0; w < 8; w++) s += red[w];

    float inv = 1.f / s;
#pragma unroll
    for (int i = 0; i < 8; i++) {
        float a = v[i] * inv;
        p[t + i * 256] = a;
        if (attn_out) attn_out[row * SEQ + t + i * 256] = a;
    }
}

// ---------------------------------------------------------------------------
extern "C" void kernel_launch(void* const* d_in, const int* in_sizes, int n_in,
                              void* d_out, int out_size)
{
    const float* q  = (const float*)d_in[0];
    const float* k  = (const float*)d_in[1];
    const float* v  = (const float*)d_in[2];
    const float* pe = (const float*)d_in[3];  // [10000, 1024]; only first 2048 rows used
    const float* Uq = (const float*)d_in[4];
    const float* Uk = (const float*)d_in[5];
    float* out = (float*)d_out;

    float *qpe, *kpe, *bias, *scores;
    cudaGetSymbolAddress((void**)&qpe,    g_qpe);
    cudaGetSymbolAddress((void**)&kpe,    g_kpe);
    cudaGetSymbolAddress((void**)&bias,   g_bias);
    cudaGetSymbolAddress((void**)&scores, g_scores);

    const float invScale = 1.0f / 11.313708498984761f;  // 1/sqrt(2*64)

    const long long ctxElems  = (long long)NB * SEQ * DM;   //  8388608
    const long long attnElems = (long long)NB * SEQ * SEQ;  // 16777216

    float* ctxOut  = out;
    float* attnOut = nullptr;
    if ((long long)out_size == ctxElems + attnElems) {
        attnOut = out + ctxElems;                    // (context, attn) concatenated
    } else if ((long long)out_size == attnElems) {
        attnOut = out; ctxOut = nullptr;             // attn only
    }                                                // else: context only

    // 1) q_pe = pe[:2048] @ Uq ;  k_pe = pe[:2048] @ Uk      (NN)
    sgemm_kernel<0, 0, 0><<<dim3(DM / BN, SEQ / BM, 1), 256>>>(
        pe, 0, Uq, 0, qpe, 0, nullptr, SEQ, DM, DM, 1.f);
    sgemm_kernel<0, 0, 0><<<dim3(DM / BN, SEQ / BM, 1), 256>>>(
        pe, 0, Uk, 0, kpe, 0, nullptr, SEQ, DM, DM, 1.f);

    // 2) bias = q_pe @ k_pe^T  (NT), computed once for all batches
    sgemm_kernel<1, 0, 0><<<dim3(SEQ / BN, SEQ / BM, 1), 256>>>(
        qpe, 0, kpe, 0, bias, 0, nullptr, SEQ, SEQ, DM, 1.f);

    // 3) scores_b = (q_b @ k_b^T + bias) * invScale   (NT, batched over z)
    sgemm_kernel<1, 0, 1><<<dim3(SEQ / BN, SEQ / BM, NB), 256>>>(
        q, (long long)SEQ * DM, k, (long long)SEQ * DM,
        scores, (long long)SEQ * SEQ, bias,
        SEQ, SEQ, DM, invScale);

    // 4) row softmax in place (mirrors into attn output region if required)
    softmax_kernel<<<NB * SEQ, 256>>>(scores, attnOut);

    // 5) context^T: out[b, d*2048 + q] = sum_k attn[b,q,k] * v[b,k,d]
    //    (NN GEMM with transposed store — implements swapaxes(1,2).reshape)
    if (ctxOut) {
        sgemm_kernel<0, 1, 0><<<dim3(DM / BN, SEQ / BM, NB), 256>>>(
            scores, (long long)SEQ * SEQ, v, (long long)SEQ * DM,
            ctxOut, (long long)SEQ * DM, nullptr,
            SEQ, DM, SEQ, 1.f);
    }
}

// round 4
// speedup vs baseline: 2.7099x; 2.5736x over previous
#include <cuda_runtime.h>
#include <cuda_bf16.h>
#include <math.h>
#include <stdint.h>

#define SEQ 2048
#define DM  1024
#define NB  4

static constexpr size_t NQ  = (size_t)NB * SEQ * DM;    //  8388608
static constexpr size_t NSS = (size_t)NB * SEQ * SEQ;   // 16777216
static constexpr size_t NP  = (size_t)SEQ * DM;         //  2097152
static constexpr size_t NU  = (size_t)DM * DM;          //  1048576

// ---- scratch (static device globals; no allocation) ----
__device__ __nv_bfloat16 g_qhi[NQ],  g_qlo[NQ];
__device__ __nv_bfloat16 g_khi[NQ],  g_klo[NQ];
__device__ __nv_bfloat16 g_vthi[NQ], g_vtlo[NQ];
__device__ __nv_bfloat16 g_ahi[NSS], g_alo[NSS];
__device__ __nv_bfloat16 g_pehi[NP];
__device__ __nv_bfloat16 g_uqt[NU],  g_ukt[NU];
__device__ __nv_bfloat16 g_qpe[NP],  g_kpe[NP];
__device__ float         g_bias[(size_t)SEQ * SEQ];
__device__ float         g_scores[NSS];

// ------------------------------- PTX helpers -------------------------------
__device__ __forceinline__ uint32_t s2u(const void* p) {
    uint32_t a;
    asm("{ .reg .u64 t; cvta.to.shared.u64 t, %1; cvt.u32.u64 %0, t; }"
        : "=r"(a) : "l"(p));
    return a;
}
__device__ __forceinline__ void cpa16(uint32_t dst, const void* src) {
    asm volatile("cp.async.cg.shared.global [%0], [%1], 16;" :: "r"(dst), "l"(src) : "memory");
}
#define LDSM4(r, addr) \
    asm volatile("ldmatrix.sync.aligned.m8n8.x4.shared.b16 {%0,%1,%2,%3}, [%4];" \
        : "=r"((r)[0]), "=r"((r)[1]), "=r"((r)[2]), "=r"((r)[3]) : "r"(addr))
#define MMA_BF16(d, a, b0, b1) \
    asm volatile("mma.sync.aligned.m16n8k16.row.col.f32.bf16.bf16.f32 " \
        "{%0,%1,%2,%3}, {%4,%5,%6,%7}, {%8,%9}, {%0,%1,%2,%3};" \
        : "+f"((d)[0]), "+f"((d)[1]), "+f"((d)[2]), "+f"((d)[3]) \
        : "r"((a)[0]), "r"((a)[1]), "r"((a)[2]), "r"((a)[3]), "r"(b0), "r"(b1))

// ---------------------------------------------------------------------------
// bf16 HMMA GEMM: C[M,N] = alpha * (sum_passes A_p @ B_p^T [+ bias])
//   A: [M,Kt] bf16 K-major, B: [N,Kt] bf16 K-major
//   PASSES==3: Ahi*Bhi + Ahi*Blo + Alo*Bhi      PASSES==1: Ahi*Bhi
//   OUTMODE: 0 = fp32 row-major (+bias, *alpha); 1 = bf16 row-major
//   CTA tile 128x128, BK=32, 256 threads (8 warps, warp tile 32x64),
//   2-stage cp.async pipeline, padded SMEM rows (80B) for conflict-free ldmatrix.
// ---------------------------------------------------------------------------
template<int PASSES, int OUTMODE>
__global__ void __launch_bounds__(256, 1)
hgemm(const __nv_bfloat16* __restrict__ Ahi, const __nv_bfloat16* __restrict__ Alo,
      const __nv_bfloat16* __restrict__ Bhi, const __nv_bfloat16* __restrict__ Blo,
      void* __restrict__ Cp, const float* __restrict__ bias, int Kt, int Ng,
      long long aStr, long long bStr, long long cStr, float alpha)
{
    extern __shared__ __align__(128) char smem[];
    constexpr int RSTRIDE = 80;                     // bytes per SMEM row (32 bf16 + pad)
    constexpr int TSZ = 128 * RSTRIDE;              // 10240 B per tile
    constexpr int NT  = (PASSES == 3) ? 4 : 2;      // tiles per stage
    constexpr int STAGE = NT * TSZ;

    const uint32_t sb = s2u(smem);
    const int tid = threadIdx.x;
    const int lane = tid & 31;
    const int wid = tid >> 5;
    const int warp_m = wid & 3;                      // 4 warps along M
    const int warp_n = wid >> 2;                     // 2 warps along N
    const int bm = blockIdx.y * 128, bn = blockIdx.x * 128, bz = blockIdx.z;
    const int NC = Kt >> 5;                          // chunks of BK=32

    const __nv_bfloat16* Abase[2] = { Ahi + (long long)bz * aStr,
                                      (PASSES == 3) ? Alo + (long long)bz * aStr : nullptr };
    const __nv_bfloat16* Bbase[2] = { Bhi + (long long)bz * bStr,
                                      (PASSES == 3) ? Blo + (long long)bz * bStr : nullptr };

    auto load_chunk = [&](int c) {
        const uint32_t stg = sb + (c & 1) * STAGE;
        const long long kc = (long long)c << 5;
        #pragma unroll
        for (int it = 0; it < NT * 2; it++) {
            const int idx = tid + it * 256;          // NT*512 chunks of 16B
            const int t4  = idx >> 9;                // tile id
            const int r   = (idx >> 2) & 127;        // row in tile
            const int c16 = idx & 3;                 // 16B chunk in row
            const __nv_bfloat16* src;
            int rowg;
            if (PASSES == 3) {
                if (t4 < 2) { src = Abase[t4]; rowg = bm + r; }
                else        { src = Bbase[t4 - 2]; rowg = bn + r; }
            } else {
                if (t4 == 0) { src = Abase[0]; rowg = bm + r; }
                else         { src = Bbase[0]; rowg = bn + r; }
            }
            cpa16(stg + t4 * TSZ + r * RSTRIDE + c16 * 16,
                  src + (long long)rowg * Kt + kc + c16 * 8);
        }
        asm volatile("cp.async.commit_group;" ::: "memory");
    };

    float acc[2][8][4];
    #pragma unroll
    for (int f = 0; f < 2; f++)
        #pragma unroll
        for (int j = 0; j < 8; j++)
            #pragma unroll
            for (int e = 0; e < 4; e++) acc[f][j][e] = 0.f;

    load_chunk(0);

    // ldmatrix lane addressing: lanes 0-15 -> rows (k0-7), lanes 16-31 -> rows (k8-15)
    const int lrow = lane & 15;
    const int lkof = (lane >> 4) * 16;               // bytes

    for (int c = 0; c < NC; c++) {
        if (c + 1 < NC) {
            load_chunk(c + 1);
            asm volatile("cp.async.wait_group 1;" ::: "memory");
        } else {
            asm volatile("cp.async.wait_group 0;" ::: "memory");
        }
        __syncthreads();
        const uint32_t stg = sb + (c & 1) * STAGE;
        const uint32_t aOff = stg + (warp_m * 32 + lrow) * RSTRIDE + lkof;
        const uint32_t bOff = stg + ((PASSES == 3 ? 2 : 1) * TSZ)
                            + (warp_n * 64 + lrow) * RSTRIDE + lkof;
        #pragma unroll
        for (int ks = 0; ks < 2; ks++) {
            const uint32_t kb = ks * 32;             // 16 elems = 32 bytes
            uint32_t ah[2][4], bh[4][4];
            #pragma unroll
            for (int f = 0; f < 2; f++) LDSM4(ah[f], aOff + f * 16 * RSTRIDE + kb);
            #pragma unroll
            for (int g = 0; g < 4; g++) LDSM4(bh[g], bOff + g * 16 * RSTRIDE + kb);
            if (PASSES == 3) {
                uint32_t al[2][4], bl[4][4];
                #pragma unroll
                for (int f = 0; f < 2; f++) LDSM4(al[f], aOff + TSZ + f * 16 * RSTRIDE + kb);
                #pragma unroll
                for (int g = 0; g < 4; g++) LDSM4(bl[g], bOff + TSZ + g * 16 * RSTRIDE + kb);
                #pragma unroll
                for (int f = 0; f < 2; f++)
                    #pragma unroll
                    for (int g = 0; g < 4; g++) {
                        MMA_BF16(acc[f][2 * g + 0], ah[f], bh[g][0], bh[g][2]);
                        MMA_BF16(acc[f][2 * g + 1], ah[f], bh[g][1], bh[g][3]);
                        MMA_BF16(acc[f][2 * g + 0], ah[f], bl[g][0], bl[g][2]);
                        MMA_BF16(acc[f][2 * g + 1], ah[f], bl[g][1], bl[g][3]);
                        MMA_BF16(acc[f][2 * g + 0], al[f], bh[g][0], bh[g][2]);
                        MMA_BF16(acc[f][2 * g + 1], al[f], bh[g][1], bh[g][3]);
                    }
            } else {
                #pragma unroll
                for (int f = 0; f < 2; f++)
                    #pragma unroll
                    for (int g = 0; g < 4; g++) {
                        MMA_BF16(acc[f][2 * g + 0], ah[f], bh[g][0], bh[g][2]);
                        MMA_BF16(acc[f][2 * g + 1], ah[f], bh[g][1], bh[g][3]);
                    }
            }
        }
        __syncthreads();
    }

    // ------------------------------- epilogue -------------------------------
    const int qrow = lane >> 2;
    const int qcol = (lane & 3) * 2;
    #pragma unroll
    for (int f = 0; f < 2; f++) {
        const int m0 = bm + warp_m * 32 + f * 16 + qrow;
        #pragma unroll
        for (int j = 0; j < 8; j++) {
            const int n = bn + warp_n * 64 + j * 8 + qcol;
            if (OUTMODE == 0) {
                float* Cf = (float*)Cp + (long long)bz * cStr;
                float2 v0 = make_float2(acc[f][j][0], acc[f][j][1]);
                float2 v1 = make_float2(acc[f][j][2], acc[f][j][3]);
                if (bias) {
                    float2 b0 = *(const float2*)(bias + (long long)m0 * Ng + n);
                    float2 b1 = *(const float2*)(bias + (long long)(m0 + 8) * Ng + n);
                    v0.x += b0.x; v0.y += b0.y; v1.x += b1.x; v1.y += b1.y;
                }
                v0.x *= alpha; v0.y *= alpha; v1.x *= alpha; v1.y *= alpha;
                *(float2*)(Cf + (long long)m0 * Ng + n) = v0;
                *(float2*)(Cf + (long long)(m0 + 8) * Ng + n) = v1;
            } else {
                __nv_bfloat16* Cb = (__nv_bfloat16*)Cp;
                __nv_bfloat162 h0, h1;
                h0.x = __float2bfloat16_rn(acc[f][j][0]);
                h0.y = __float2bfloat16_rn(acc[f][j][1]);
                h1.x = __float2bfloat16_rn(acc[f][j][2]);
                h1.y = __float2bfloat16_rn(acc[f][j][3]);
                *(__nv_bfloat162*)(Cb + (long long)m0 * Ng + n) = h0;
                *(__nv_bfloat162*)(Cb + (long long)(m0 + 8) * Ng + n) = h1;
            }
        }
    }
}

// ------------------------- fp32 -> bf16 hi/lo split -------------------------
template<int WLO>
__global__ __launch_bounds__(256)
void split_k(const float4* __restrict__ src, __nv_bfloat16* __restrict__ hi,
             __nv_bfloat16* __restrict__ lo, int n4)
{
    int i = blockIdx.x * 256 + threadIdx.x;
    if (i >= n4) return;
    float4 x = src[i];
    __nv_bfloat16 h0 = __float2bfloat16_rn(x.x), h1 = __float2bfloat16_rn(x.y);
    __nv_bfloat16 h2 = __float2bfloat16_rn(x.z), h3 = __float2bfloat16_rn(x.w);
    __nv_bfloat162 H0; H0.x = h0; H0.y = h1;
    __nv_bfloat162 H1; H1.x = h2; H1.y = h3;
    ((__nv_bfloat162*)hi)[2 * i]     = H0;
    ((__nv_bfloat162*)hi)[2 * i + 1] = H1;
    if (WLO) {
        __nv_bfloat162 L0, L1;
        L0.x = __float2bfloat16_rn(x.x - __bfloat162float(h0));
        L0.y = __float2bfloat16_rn(x.y - __bfloat162float(h1));
        L1.x = __float2bfloat16_rn(x.z - __bfloat162float(h2));
        L1.y = __float2bfloat16_rn(x.w - __bfloat162float(h3));
        ((__nv_bfloat162*)lo)[2 * i]     = L0;
        ((__nv_bfloat162*)lo)[2 * i + 1] = L1;
    }
}

// ------------------- transpose + split: dst[c][r] = src[r][c] ---------------
template<int WLO>
__global__ __launch_bounds__(256)
void tsplit_k(const float* __restrict__ src, __nv_bfloat16* __restrict__ hi,
              __nv_bfloat16* __restrict__ lo, int R, int C,
              long long sStr, long long dStr)
{
    __shared__ float tile[32][33];
    src += (long long)blockIdx.z * sStr;
    const int c0 = blockIdx.x * 32, r0 = blockIdx.y * 32;
    const int tx = threadIdx.x, ty = threadIdx.y;   // block (32,8)
    #pragma unroll
    for (int i = 0; i < 4; i++)
        tile[ty + i * 8][tx] = src[(long long)(r0 + ty + i * 8) * C + c0 + tx];
    __syncthreads();
    #pragma unroll
    for (int i = 0; i < 4; i++) {
        float v = tile[tx][ty + i * 8];
        __nv_bfloat16 h = __float2bfloat16_rn(v);
        long long o = (long long)blockIdx.z * dStr + (long long)(c0 + ty + i * 8) * R + r0 + tx;
        hi[o] = h;
        if (WLO) lo[o] = __float2bfloat16_rn(v - __bfloat162float(h));
    }
}

// ------------------------------- softmax ------------------------------------
__global__ __launch_bounds__(256)
void softmax_kernel(const float* __restrict__ scores, float* __restrict__ attn_out,
                    __nv_bfloat16* __restrict__ ahi, __nv_bfloat16* __restrict__ alo)
{
    const size_t row = blockIdx.x;
    const float* p = scores + row * SEQ;
    const int t = threadIdx.x;
    __shared__ float red[8];

    float v[8];
    float mx = -INFINITY;
    #pragma unroll
    for (int i = 0; i < 8; i++) { v[i] = p[t + i * 256]; mx = fmaxf(mx, v[i]); }
    #pragma unroll
    for (int o = 16; o; o >>= 1) mx = fmaxf(mx, __shfl_xor_sync(0xffffffffu, mx, o));
    if ((t & 31) == 0) red[t >> 5] = mx;
    __syncthreads();
    mx = red[0];
    #pragma unroll
    for (int w = 1; w < 8; w++) mx = fmaxf(mx, red[w]);
    __syncthreads();

    float s = 0.f;
    #pragma unroll
    for (int i = 0; i < 8; i++) { v[i] = __expf(v[i] - mx); s += v[i]; }
    #pragma unroll
    for (int o = 16; o; o >>= 1) s += __shfl_xor_sync(0xffffffffu, s, o);
    if ((t & 31) == 0) red[t >> 5] = s;
    __syncthreads();
    s = 0.f;
    #pragma unroll
    for (int w = 0; w < 8; w++) s += red[w];

    const float inv = 1.f / s;
    #pragma unroll
    for (int i = 0; i < 8; i++) {
        const float a = v[i] * inv;
        const size_t idx = row * SEQ + t + i * 256;
        if (attn_out) attn_out[idx] = a;
        if (ahi) {
            __nv_bfloat16 h = __float2bfloat16_rn(a);
            ahi[idx] = h;
            alo[idx] = __float2bfloat16_rn(a - __bfloat162float(h));
        }
    }
}

// ---------------------------------------------------------------------------
extern "C" void kernel_launch(void* const* d_in, const int* in_sizes, int n_in,
                              void* d_out, int out_size)
{
    const float* q  = (const float*)d_in[0];
    const float* k  = (const float*)d_in[1];
    const float* v  = (const float*)d_in[2];
    const float* pe = (const float*)d_in[3];
    const float* Uq = (const float*)d_in[4];
    const float* Uk = (const float*)d_in[5];
    float* out = (float*)d_out;

    __nv_bfloat16 *qhi, *qlo, *khi, *klo, *vthi, *vtlo, *ahi, *alo;
    __nv_bfloat16 *pehi, *uqt, *ukt, *qpe, *kpe;
    float *bias, *scores;
    cudaGetSymbolAddress((void**)&qhi,  g_qhi);   cudaGetSymbolAddress((void**)&qlo,  g_qlo);
    cudaGetSymbolAddress((void**)&khi,  g_khi);   cudaGetSymbolAddress((void**)&klo,  g_klo);
    cudaGetSymbolAddress((void**)&vthi, g_vthi);  cudaGetSymbolAddress((void**)&vtlo, g_vtlo);
    cudaGetSymbolAddress((void**)&ahi,  g_ahi);   cudaGetSymbolAddress((void**)&alo,  g_alo);
    cudaGetSymbolAddress((void**)&pehi, g_pehi);
    cudaGetSymbolAddress((void**)&uqt,  g_uqt);   cudaGetSymbolAddress((void**)&ukt,  g_ukt);
    cudaGetSymbolAddress((void**)&qpe,  g_qpe);   cudaGetSymbolAddress((void**)&kpe,  g_kpe);
    cudaGetSymbolAddress((void**)&bias, g_bias);  cudaGetSymbolAddress((void**)&scores, g_scores);

    const float invScale = 1.0f / 11.313708498984761f;  // 1/sqrt(2*64)

    const long long ctxElems  = (long long)NB * SEQ * DM;
    const long long attnElems = (long long)NB * SEQ * SEQ;
    float* ctxOut  = out;
    float* attnOut = nullptr;
    if ((long long)out_size == ctxElems + attnElems) {
        attnOut = out + ctxElems;
    } else if ((long long)out_size == attnElems) {
        attnOut = out; ctxOut = nullptr;
    }

    const int SM3 = 2 * 4 * 128 * 80;   // 81920 B
    const int SM1 = 2 * 2 * 128 * 80;   // 40960 B
    cudaFuncSetAttribute(hgemm<3, 0>, cudaFuncAttributeMaxDynamicSharedMemorySize, SM3);
    cudaFuncSetAttribute(hgemm<1, 0>, cudaFuncAttributeMaxDynamicSharedMemorySize, SM1);
    cudaFuncSetAttribute(hgemm<1, 1>, cudaFuncAttributeMaxDynamicSharedMemorySize, SM1);

    // ---- splits ----
    split_k<1><<<(int)(NQ / 4 / 256), 256>>>((const float4*)q, qhi, qlo, (int)(NQ / 4));
    split_k<1><<<(int)(NQ / 4 / 256), 256>>>((const float4*)k, khi, klo, (int)(NQ / 4));
    split_k<0><<<(int)(NP / 4 / 256), 256>>>((const float4*)pe, pehi, nullptr, (int)(NP / 4));
    tsplit_k<0><<<dim3(DM / 32, DM / 32, 1), dim3(32, 8)>>>(Uq, uqt, nullptr, DM, DM, 0, 0);
    tsplit_k<0><<<dim3(DM / 32, DM / 32, 1), dim3(32, 8)>>>(Uk, ukt, nullptr, DM, DM, 0, 0);
    if (ctxOut)
        tsplit_k<1><<<dim3(DM / 32, SEQ / 32, NB), dim3(32, 8)>>>(
            v, vthi, vtlo, SEQ, DM, (long long)SEQ * DM, (long long)SEQ * DM);

    // ---- TUPE bias chain (single-pass bf16) ----
    hgemm<1, 1><<<dim3(DM / 128, SEQ / 128, 1), 256, SM1>>>(
        pehi, nullptr, uqt, nullptr, qpe, nullptr, DM, DM, 0, 0, 0, 1.f);
    hgemm<1, 1><<<dim3(DM / 128, SEQ / 128, 1), 256, SM1>>>(
        pehi, nullptr, ukt, nullptr, kpe, nullptr, DM, DM, 0, 0, 0, 1.f);
    hgemm<1, 0><<<dim3(SEQ / 128, SEQ / 128, 1), 256, SM1>>>(
        qpe, nullptr, kpe, nullptr, bias, nullptr, DM, SEQ, 0, 0, 0, 1.f);

    // ---- scores = (q@k^T + bias) * invScale  (3-pass bf16) ----
    hgemm<3, 0><<<dim3(SEQ / 128, SEQ / 128, NB), 256, SM3>>>(
        qhi, qlo, khi, klo, scores, bias, DM, SEQ,
        (long long)SEQ * DM, (long long)SEQ * DM, (long long)SEQ * SEQ, invScale);

    // ---- softmax (emits attn fp32 and/or bf16 hi/lo) ----
    softmax_kernel<<<NB * SEQ, 256>>>(scores, attnOut,
                                      ctxOut ? ahi : nullptr, ctxOut ? alo : nullptr);

    // ---- ctx^T = v^T @ attn^T  (3-pass bf16, NT, row-major out == swapaxes layout) ----
    if (ctxOut)
        hgemm<3, 0><<<dim3(SEQ / 128, DM / 128, NB), 256, SM3>>>(
            vthi, vtlo, ahi, alo, ctxOut, nullptr, SEQ, SEQ,
            (long long)SEQ * DM, (long long)SEQ * SEQ, (long long)SEQ * DM, 1.f);
}